// round 14
// baseline (speedup 1.0000x reference)
#include <cuda_runtime.h>
#include <cstdint>
#include <math.h>

// ---------------------------------------------------------------------------
// SpatialBayesianLayer: BitLinear(2F->F) -> ReLU -> BitLinear(F->F) -> sigmoid
//                       -> posterior = prior*lik / sum_S(prior*lik)
// Exact-int8 tensor-core implementation (mma.sync m16n8k32.s8).
// R14: phase-A load batching 4->8 rows (MLP 16); two dummy launches align the
//      ncu capture window onto bitnet_F (position 3 in the stream).
// ---------------------------------------------------------------------------

#define QBF 127.0f
#define EPSF 1e-5f
#define MAGF 12582912.0f          // 1.5 * 2^23
#define MAG_I 0x4B400000          // bits of MAGF
#define L2E 1.4426950408889634f

#define NTILES  2048
#define GRIDP   296               // 2 x 148 persistent CTAs
#define BASEQ   6                 // 2048 = 296*6 + 272 -> first 272 CTAs get 7

// ---- device scratch (no runtime allocation allowed) ----
__device__ int8_t g_W1q[128 * 256];
__device__ int8_t g_W2q[128 * 128];
__device__ float  g_wsc[2];        // mean |w| per layer (ref's 1/ws)
__device__ double g_norm[1024];    // per (batch, feature) normalizer accumulators
__device__ float  g_rnorm[1024];   // reciprocal normalizers

// ---- shared memory layout for bitnet_F (bytes) ----
// strides 272 and 144 are both ==4 words mod 32 -> LDSM phases conflict-free
#define OFF_XQ     0
#define XQ_STR     272
#define OFF_W1     34816
#define W1_STR     272
#define OFF_W2     69632
#define W2_STR     144
#define OFF_HQ     88064
#define HQ_STR     144
#define OFF_S1     106496      // 128 floats (warp-private 16-row slices)
#define OFF_B1     107008
#define OFF_B2L    107520      // -b2 * log2(e)
#define OFF_CSW    108032      // per-warp column sums: 8 x 128 floats
#define SMEM_BYTES 112128

// ---------------------------------------------------------------------------
__device__ __forceinline__ void mma_s8(int* c,
                                       unsigned a0, unsigned a1, unsigned a2, unsigned a3,
                                       unsigned b0, unsigned b1) {
    asm volatile(
        "mma.sync.aligned.m16n8k32.row.col.s32.s8.s8.s32 "
        "{%0,%1,%2,%3}, {%4,%5,%6,%7}, {%8,%9}, {%0,%1,%2,%3};"
        : "+r"(c[0]), "+r"(c[1]), "+r"(c[2]), "+r"(c[3])
        : "r"(a0), "r"(a1), "r"(a2), "r"(a3), "r"(b0), "r"(b1));
}

__device__ __forceinline__ void ldsm4(unsigned& r0, unsigned& r1,
                                      unsigned& r2, unsigned& r3, uint32_t addr) {
    asm volatile("ldmatrix.sync.aligned.m8n8.x4.shared.b16 {%0,%1,%2,%3}, [%4];"
                 : "=r"(r0), "=r"(r1), "=r"(r2), "=r"(r3) : "r"(addr));
}

__device__ __forceinline__ void cp16(uint32_t dst, const void* src) {
    asm volatile("cp.async.cg.shared.global [%0], [%1], 16;" :: "r"(dst), "l"(src));
}

__device__ __forceinline__ uint32_t smem_u32(const void* p) {
    uint32_t a;
    asm("{ .reg .u64 t; cvta.to.shared.u64 t, %1; cvt.u32.u64 %0, t; }"
        : "=r"(a) : "l"(p));
    return a;
}

__device__ __forceinline__ float ex2f(float x) {
    float r;
    asm("ex2.approx.f32 %0, %1;" : "=f"(r) : "f"(x));
    return r;
}

// single-instruction max-reduce over membermask (nonneg floats via uint bits)
__device__ __forceinline__ unsigned redux_max(unsigned v, unsigned mask) {
    unsigned r;
    asm("redux.sync.max.u32 %0, %1, %2;" : "=r"(r) : "r"(v), "r"(mask));
    return r;
}

// round(v.i * s) for |v*s| <= 127, bit-exact vs rintf: FADD at 1.5*2^23 rounds
// half-to-even; low byte of float bits IS the int8 (two's complement).
__device__ __forceinline__ unsigned pack_magic4(float4 v, float s) {
    unsigned b0 = __float_as_uint(__fadd_rn(__fmul_rn(v.x, s), MAGF));
    unsigned b1 = __float_as_uint(__fadd_rn(__fmul_rn(v.y, s), MAGF));
    unsigned b2 = __float_as_uint(__fadd_rn(__fmul_rn(v.z, s), MAGF));
    unsigned b3 = __float_as_uint(__fadd_rn(__fmul_rn(v.w, s), MAGF));
    unsigned r01 = __byte_perm(b0, b1, 0x0040);
    unsigned r23 = __byte_perm(b2, b3, 0x0040);
    return __byte_perm(r01, r23, 0x5410);
}

// exact int->float for |q| < 2^22 without I2F
__device__ __forceinline__ float i2f_magic(int q) {
    return __int_as_float(q + MAG_I) - MAGF;
}

// ---------------------------------------------------------------------------
// Kernel 1: weight ternarization (absmean scale) + zero normalizers.
// ---------------------------------------------------------------------------
__global__ void prep_kernel(const float* __restrict__ W1,
                            const float* __restrict__ W2) {
    __shared__ double red[1024];
    __shared__ float s_ws;
    const int tid = threadIdx.x;
    const float* W = (blockIdx.x == 0) ? W1 : W2;
    int8_t* Wq     = (blockIdx.x == 0) ? g_W1q : g_W2q;
    const int n    = (blockIdx.x == 0) ? 128 * 256 : 128 * 128;

    if (tid < 512) g_norm[blockIdx.x * 512 + tid] = 0.0;

    double acc = 0.0;
    for (int i = tid; i < n; i += 1024) acc += (double)fabsf(W[i]);
    red[tid] = acc;
    __syncthreads();
    for (int s = 512; s > 0; s >>= 1) {
        if (tid < s) red[tid] += red[tid + s];
        __syncthreads();
    }
    if (tid == 0) {
        float m  = fmaxf((float)(red[0] / (double)n), EPSF);
        s_ws = 1.0f / m;                 // ref: ws = 1/clip(mean)
        g_wsc[blockIdx.x] = m;           // ref's t/ws (t = +-1) -> t*m
    }
    __syncthreads();
    const float ws = s_ws;
    for (int i = tid; i < n; i += 1024) {
        float t = rintf(W[i] * ws);      // round half-to-even like jnp.round
        t = fminf(1.0f, fmaxf(-1.0f, t));
        Wq[i] = (int8_t)t;
    }
}

// ---------------------------------------------------------------------------
// no-op kernels: shift the ncu capture window so bitnet_F sits at launch
// position 3 in the stream (observed capture slot).
// ---------------------------------------------------------------------------
__global__ void dummy_kernel() {}

// ---------------------------------------------------------------------------
// Kernel 2: fused persistent pass, contiguous tile chunk per CTA.
// Warps fully decoupled; per-warp smem column sums, flushed on batch change.
// ---------------------------------------------------------------------------
__global__ __launch_bounds__(256, 2)
void bitnet_F(const float* __restrict__ evid, const float* __restrict__ prior,
              const float* __restrict__ b1, const float* __restrict__ b2,
              float* __restrict__ out) {
    extern __shared__ unsigned char sm[];
    const uint32_t sb = smem_u32(sm);
    const int tid   = threadIdx.x;
    const int lane  = tid & 31;
    const int w     = tid >> 5;
    const int g     = lane >> 2;   // mma group id (row)
    const int tg    = lane & 3;    // thread-in-group (col/k)
    const int mb    = w * 16;
    const unsigned qmask = 0xFu << (lane & 28);   // this lane's quad

    // ldmatrix per-lane address components
    const int lrow  = lane & 15;
    const int lkoff = (lane >> 4) * 16;
    const int brow  = ((lane >> 4) & 1) * 8 + (lane & 7);
    const int bkoff = ((lane >> 3) & 1) * 16;

    float* s1arr = (float*)(sm + OFF_S1);
    float* b1s   = (float*)(sm + OFF_B1);
    float* b2l   = (float*)(sm + OFF_B2L);
    float* csw   = (float*)(sm + OFF_CSW) + w * 128;   // warp-private
    const float2* prior2 = (const float2*)prior;
    const float4* pr4 = (const float4*)prior;
    const float4* ev4 = (const float4*)evid;

    // ---- prologue: weight tiles once ----
#pragma unroll
    for (int i = 0; i < 8; i++) {            // W1: 2048 x 16B
        int c = tid + 256 * i;
        int o = c >> 4, k = c & 15;
        cp16(sb + OFF_W1 + o * W1_STR + k * 16, g_W1q + c * 16);
    }
#pragma unroll
    for (int i = 0; i < 4; i++) {            // W2: 1024 x 16B
        int c = tid + 256 * i;
        int o = c >> 3, k = c & 7;
        cp16(sb + OFF_W2 + o * W2_STR + k * 16, g_W2q + c * 16);
    }
    if (tid < 128) {
        b1s[tid] = __ldg(&b1[tid]);
        b2l[tid] = -__ldg(&b2[tid]) * L2E;   // folded sigmoid bias
    }
#pragma unroll
    for (int c = 0; c < 4; c++) csw[lane + c * 32] = 0.0f;   // zero own csum
    asm volatile("cp.async.commit_group;");
    asm volatile("cp.async.wait_group 0;" ::: "memory");
    __syncthreads();                          // weights/biases visible to all

    const float wsc1 = g_wsc[0];
    const float wsc2 = g_wsc[1];

    // tile-invariant LDSM bases
    const uint32_t aAbase  = sb + OFF_XQ + (mb + lrow) * XQ_STR + lkoff;
    const uint32_t aHbase  = sb + OFF_HQ + (mb + lrow) * HQ_STR + lkoff;
    const uint32_t bW1base = sb + OFF_W1 + brow * W1_STR + bkoff;
    const uint32_t bW2base = sb + OFF_W2 + brow * W2_STR + bkoff;

    // contiguous chunk: batch boundary crossed at most once per CTA
    const int bid    = blockIdx.x;
    const int tstart = bid * BASEQ + (bid < 272 ? bid : 272);
    const int tend   = tstart + BASEQ + (bid < 272 ? 1 : 0);
    int cur_batch = tstart >> 8;               // 256 tiles per batch

    for (int tile = tstart; tile < tend; tile++) {
        const int token0 = tile * 128;
        const int batch  = token0 >> 15;

        if (batch != cur_batch) {              // flush warp csum (rare: <=1x)
            __syncwarp();
#pragma unroll
            for (int c = 0; c < 4; c++) {
                int col = lane + c * 32;
                float v = csw[col];
                if (v != 0.0f) atomicAdd(&g_norm[cur_batch * 128 + col], (double)v);
                csw[col] = 0.0f;
            }
            __syncwarp();
            cur_batch = batch;
        }

        // ---- Phase A: quantize own 16-row band (batch 8 rows, MLP 16) ----
        {
            const size_t rbase = (size_t)(token0 + mb) * 32;   // float4 units
#pragma unroll
            for (int half = 0; half < 2; half++) {
                float4 pa[8], ea[8];
#pragma unroll
                for (int r = 0; r < 8; r++) {
                    pa[r] = __ldg(&pr4[rbase + (size_t)(half * 8 + r) * 32 + lane]);
                    ea[r] = __ldg(&ev4[rbase + (size_t)(half * 8 + r) * 32 + lane]);
                }
#pragma unroll
                for (int r = 0; r < 8; r++) {
                    float4 a = pa[r], b = ea[r];
                    float m = fmaxf(fmaxf(fabsf(a.x), fabsf(a.y)),
                                    fmaxf(fabsf(a.z), fabsf(a.w)));
                    m = fmaxf(m, fmaxf(fmaxf(fabsf(b.x), fabsf(b.y)),
                                       fmaxf(fabsf(b.z), fabsf(b.w))));
                    m = __uint_as_float(redux_max(__float_as_uint(m), 0xffffffffu));
                    float s = QBF / fmaxf(m, EPSF);
                    const int row = mb + half * 8 + r;
                    *(unsigned*)(sm + OFF_XQ + row * XQ_STR + lane * 4) =
                        pack_magic4(a, s);
                    *(unsigned*)(sm + OFF_XQ + row * XQ_STR + 128 + lane * 4) =
                        pack_magic4(b, s);
                    if (lane == 0) s1arr[row] = s;
                }
            }
        }
        __syncwarp();   // band + scales are warp-private

        // ---- GEMM1: [16 x 256] x [256 x 128] per warp, int8 exact ----
        int acc[16][4];
#pragma unroll
        for (int n = 0; n < 16; n++) { acc[n][0] = acc[n][1] = acc[n][2] = acc[n][3] = 0; }
#pragma unroll
        for (int k8 = 0; k8 < 8; k8++) {
            const int kb = k8 * 32;
            unsigned a0, a1, a2, a3;
            ldsm4(a0, a1, a2, a3, aAbase + kb);
#pragma unroll
            for (int n2 = 0; n2 < 8; n2++) {
                unsigned b0, b1r, b2r, b3;
                ldsm4(b0, b1r, b2r, b3, bW1base + (n2 * 16) * W1_STR + kb);
                mma_s8(acc[n2 * 2],     a0, a1, a2, a3, b0,  b1r);
                mma_s8(acc[n2 * 2 + 1], a0, a1, a2, a3, b2r, b3);
            }
        }

        // ---- Epilogue 1: dequant + bias + ReLU, quad redux max, requant ----
        const float dq0 = wsc1 / s1arr[mb + g];
        const float dq1 = wsc1 / s1arr[mb + g + 8];
        float hm0 = 0.0f, hm1 = 0.0f;
#pragma unroll
        for (int n = 0; n < 16; n++) {
            const int col = n * 8 + tg * 2;
            float c0 = fmaxf(0.0f, i2f_magic(acc[n][0]) * dq0 + b1s[col]);
            float c1 = fmaxf(0.0f, i2f_magic(acc[n][1]) * dq0 + b1s[col + 1]);
            float c2 = fmaxf(0.0f, i2f_magic(acc[n][2]) * dq1 + b1s[col]);
            float c3 = fmaxf(0.0f, i2f_magic(acc[n][3]) * dq1 + b1s[col + 1]);
            hm0 = fmaxf(hm0, fmaxf(c0, c1));
            hm1 = fmaxf(hm1, fmaxf(c2, c3));
            acc[n][0] = __float_as_int(c0);
            acc[n][1] = __float_as_int(c1);
            acc[n][2] = __float_as_int(c2);
            acc[n][3] = __float_as_int(c3);
        }
        hm0 = __uint_as_float(redux_max(__float_as_uint(hm0), qmask));
        hm1 = __uint_as_float(redux_max(__float_as_uint(hm1), qmask));
        const float s2_0 = QBF / fmaxf(hm0, EPSF);
        const float s2_1 = QBF / fmaxf(hm1, EPSF);

#pragma unroll
        for (int n = 0; n < 16; n++) {
            unsigned q0 = __float_as_uint(__fadd_rn(__fmul_rn(__int_as_float(acc[n][0]), s2_0), MAGF));
            unsigned q1 = __float_as_uint(__fadd_rn(__fmul_rn(__int_as_float(acc[n][1]), s2_0), MAGF));
            unsigned q2 = __float_as_uint(__fadd_rn(__fmul_rn(__int_as_float(acc[n][2]), s2_1), MAGF));
            unsigned q3 = __float_as_uint(__fadd_rn(__fmul_rn(__int_as_float(acc[n][3]), s2_1), MAGF));
            unsigned short p0 = (unsigned short)__byte_perm(q0, q1, 0x0040);
            unsigned short p1 = (unsigned short)__byte_perm(q2, q3, 0x0040);
            *(unsigned short*)(sm + OFF_HQ + (mb + g)     * HQ_STR + n * 8 + tg * 2) = p0;
            *(unsigned short*)(sm + OFF_HQ + (mb + g + 8) * HQ_STR + n * 8 + tg * 2) = p1;
        }
        __syncwarp();   // each warp reads only its own 16 HQ rows

        // ---- GEMM2: [16 x 128] x [128 x 128] per warp ----
#pragma unroll
        for (int n = 0; n < 16; n++) { acc[n][0] = acc[n][1] = acc[n][2] = acc[n][3] = 0; }
#pragma unroll
        for (int k4 = 0; k4 < 4; k4++) {
            const int kb = k4 * 32;
            unsigned a0, a1, a2, a3;
            ldsm4(a0, a1, a2, a3, aHbase + kb);
#pragma unroll
            for (int n2 = 0; n2 < 8; n2++) {
                unsigned b0, b1r, b2r, b3;
                ldsm4(b0, b1r, b2r, b3, bW2base + (n2 * 16) * W2_STR + kb);
                mma_s8(acc[n2 * 2],     a0, a1, a2, a3, b0,  b1r);
                mma_s8(acc[n2 * 2 + 1], a0, a1, a2, a3, b2r, b3);
            }
        }

        // ---- Epilogue 2: folded sigmoid, store, warp-private column sums ----
        const float dq20 = wsc2 / s2_0;
        const float dq21 = wsc2 / s2_1;
        const float dql0 = -dq20 * L2E;     // exp(-z) = 2^(acc*dql + b2l)
        const float dql1 = -dq21 * L2E;
        const size_t row0 = (size_t)(token0 + mb + g) * 128;
        const size_t row1 = row0 + (size_t)8 * 128;

#pragma unroll
        for (int n = 0; n < 16; n++) {
            const int col = n * 8 + tg * 2;
            float e0 = ex2f(i2f_magic(acc[n][0]) * dql0 + b2l[col]);
            float e1 = ex2f(i2f_magic(acc[n][1]) * dql0 + b2l[col + 1]);
            float e2 = ex2f(i2f_magic(acc[n][2]) * dql1 + b2l[col]);
            float e3 = ex2f(i2f_magic(acc[n][3]) * dql1 + b2l[col + 1]);
            float2 pr0 = __ldg(&prior2[(row0 + col) >> 1]);   // L2-hot (phase A)
            float2 pr1 = __ldg(&prior2[(row1 + col) >> 1]);
            float u0 = __fdividef(pr0.x, 1.0f + e0);
            float u1 = __fdividef(pr0.y, 1.0f + e1);
            float u2 = __fdividef(pr1.x, 1.0f + e2);
            float u3 = __fdividef(pr1.y, 1.0f + e3);
            *(float2*)(out + row0 + col) = make_float2(u0, u1);
            *(float2*)(out + row1 + col) = make_float2(u2, u3);
            float cs0 = u0 + u2, cs1 = u1 + u3;
            cs0 += __shfl_xor_sync(0xffffffffu, cs0, 4);
            cs0 += __shfl_xor_sync(0xffffffffu, cs0, 8);
            cs0 += __shfl_xor_sync(0xffffffffu, cs0, 16);
            cs1 += __shfl_xor_sync(0xffffffffu, cs1, 4);
            cs1 += __shfl_xor_sync(0xffffffffu, cs1, 8);
            cs1 += __shfl_xor_sync(0xffffffffu, cs1, 16);
            if (g == 0) {                     // plain warp-private smem adds
                csw[col]     += cs0;
                csw[col + 1] += cs1;
            }
        }
        // no block barrier: all loop-carried smem state is warp-private
    }

    // ---- final flush of warp csum ----
    __syncwarp();
#pragma unroll
    for (int c = 0; c < 4; c++) {
        int col = lane + c * 32;
        float v = csw[col];
        if (v != 0.0f) atomicAdd(&g_norm[cur_batch * 128 + col], (double)v);
    }
}

// ---------------------------------------------------------------------------
__global__ void finalize_norm() {
    int i = threadIdx.x;  // 1024 threads
    g_rnorm[i] = 1.0f / fmaxf((float)g_norm[i], 1e-10f);
}

// ---------------------------------------------------------------------------
__global__ void normalize_kernel(float4* __restrict__ out4) {
    int i = blockIdx.x * 256 + threadIdx.x;    // 8,388,608 float4s
    int b  = i >> 20;                          // 2^20 float4 per batch
    int f4 = i & 31;                           // 32 float4 per feature row
    float4 r = *(const float4*)&g_rnorm[b * 128 + f4 * 4];
    float4 v = out4[i];
    v.x *= r.x; v.y *= r.y; v.z *= r.z; v.w *= r.w;
    out4[i] = v;
}

// ---------------------------------------------------------------------------
extern "C" void kernel_launch(void* const* d_in, const int* in_sizes, int n_in,
                              void* d_out, int out_size) {
    const float* evid  = (const float*)d_in[0];
    const float* prior = (const float*)d_in[1];
    const float* W1    = (const float*)d_in[2];
    const float* b1    = (const float*)d_in[3];
    const float* W2    = (const float*)d_in[4];
    const float* b2    = (const float*)d_in[5];
    float* out = (float*)d_out;

    cudaFuncSetAttribute(bitnet_F, cudaFuncAttributeMaxDynamicSharedMemorySize,
                         SMEM_BYTES);

    prep_kernel<<<2, 1024>>>(W1, W2);
    dummy_kernel<<<1, 32>>>();                 // capture-window alignment
    dummy_kernel<<<1, 32>>>();                 // (bitnet_F -> stream pos 3)
    bitnet_F<<<GRIDP, 256, SMEM_BYTES>>>(evid, prior, b1, b2, out);
    finalize_norm<<<1, 1024>>>();
    normalize_kernel<<<out_size / 1024, 256>>>((float4*)out);
}

// round 16
// speedup vs baseline: 1.0638x; 1.0638x over previous
#include <cuda_runtime.h>
#include <cstdint>
#include <math.h>

// ---------------------------------------------------------------------------
// SpatialBayesianLayer: BitLinear(2F->F) -> ReLU -> BitLinear(F->F) -> sigmoid
//                       -> posterior = prior*lik / sum_S(prior*lik)
// Exact-int8 tensor-core implementation (mma.sync m16n8k32.s8).
// R15/R16: epilogue-2 smem transpose staging (coalesced LDG/STG, frag-layout
//      LDS/STS in the dead XQ band) — kills the 8-line/instr global scatter
//      that made epi2 the largest L1 consumer. Phase A at 4-row batches
//      (R14's 8-row batch spilled at the 128-reg cap).
// ---------------------------------------------------------------------------

#define QBF 127.0f
#define EPSF 1e-5f
#define MAGF 12582912.0f          // 1.5 * 2^23
#define MAG_I 0x4B400000          // bits of MAGF
#define L2E 1.4426950408889634f

#define NTILES  2048
#define GRIDP   296               // 2 x 148 persistent CTAs
#define BASEQ   6                 // 2048 = 296*6 + 272 -> first 272 CTAs get 7

// ---- device scratch (no runtime allocation allowed) ----
__device__ int8_t g_W1q[128 * 256];
__device__ int8_t g_W2q[128 * 128];
__device__ float  g_wsc[2];        // mean |w| per layer (ref's 1/ws)
__device__ double g_norm[1024];    // per (batch, feature) normalizer accumulators
__device__ float  g_rnorm[1024];   // reciprocal normalizers

// ---- shared memory layout for bitnet_F (bytes) ----
// strides 272 and 144 are both ==4 words mod 32 -> LDSM phases conflict-free
#define OFF_XQ     0
#define XQ_STR     272
#define OFF_W1     34816
#define W1_STR     272
#define OFF_W2     69632
#define W2_STR     144
#define OFF_HQ     88064
#define HQ_STR     144
#define OFF_S1     106496      // 128 floats (warp-private 16-row slices)
#define OFF_B1     107008
#define OFF_B2L    107520      // -b2 * log2(e)
#define OFF_CSW    108032      // per-warp column sums: 8 x 128 floats
#define SMEM_BYTES 112128

// ---------------------------------------------------------------------------
__device__ __forceinline__ void mma_s8(int* c,
                                       unsigned a0, unsigned a1, unsigned a2, unsigned a3,
                                       unsigned b0, unsigned b1) {
    asm volatile(
        "mma.sync.aligned.m16n8k32.row.col.s32.s8.s8.s32 "
        "{%0,%1,%2,%3}, {%4,%5,%6,%7}, {%8,%9}, {%0,%1,%2,%3};"
        : "+r"(c[0]), "+r"(c[1]), "+r"(c[2]), "+r"(c[3])
        : "r"(a0), "r"(a1), "r"(a2), "r"(a3), "r"(b0), "r"(b1));
}

__device__ __forceinline__ void ldsm4(unsigned& r0, unsigned& r1,
                                      unsigned& r2, unsigned& r3, uint32_t addr) {
    asm volatile("ldmatrix.sync.aligned.m8n8.x4.shared.b16 {%0,%1,%2,%3}, [%4];"
                 : "=r"(r0), "=r"(r1), "=r"(r2), "=r"(r3) : "r"(addr));
}

__device__ __forceinline__ void cp16(uint32_t dst, const void* src) {
    asm volatile("cp.async.cg.shared.global [%0], [%1], 16;" :: "r"(dst), "l"(src));
}

__device__ __forceinline__ uint32_t smem_u32(const void* p) {
    uint32_t a;
    asm("{ .reg .u64 t; cvta.to.shared.u64 t, %1; cvt.u32.u64 %0, t; }"
        : "=r"(a) : "l"(p));
    return a;
}

__device__ __forceinline__ float ex2f(float x) {
    float r;
    asm("ex2.approx.f32 %0, %1;" : "=f"(r) : "f"(x));
    return r;
}

// single-instruction max-reduce over membermask (nonneg floats via uint bits)
__device__ __forceinline__ unsigned redux_max(unsigned v, unsigned mask) {
    unsigned r;
    asm("redux.sync.max.u32 %0, %1, %2;" : "=r"(r) : "r"(v), "r"(mask));
    return r;
}

// round(v.i * s) for |v*s| <= 127, bit-exact vs rintf: FADD at 1.5*2^23 rounds
// half-to-even; low byte of float bits IS the int8 (two's complement).
__device__ __forceinline__ unsigned pack_magic4(float4 v, float s) {
    unsigned b0 = __float_as_uint(__fadd_rn(__fmul_rn(v.x, s), MAGF));
    unsigned b1 = __float_as_uint(__fadd_rn(__fmul_rn(v.y, s), MAGF));
    unsigned b2 = __float_as_uint(__fadd_rn(__fmul_rn(v.z, s), MAGF));
    unsigned b3 = __float_as_uint(__fadd_rn(__fmul_rn(v.w, s), MAGF));
    unsigned r01 = __byte_perm(b0, b1, 0x0040);
    unsigned r23 = __byte_perm(b2, b3, 0x0040);
    return __byte_perm(r01, r23, 0x5410);
}

// exact int->float for |q| < 2^22 without I2F
__device__ __forceinline__ float i2f_magic(int q) {
    return __int_as_float(q + MAG_I) - MAGF;
}

// ---------------------------------------------------------------------------
// Kernel 1: weight ternarization (absmean scale) + zero normalizers.
// ---------------------------------------------------------------------------
__global__ void prep_kernel(const float* __restrict__ W1,
                            const float* __restrict__ W2) {
    __shared__ double red[1024];
    __shared__ float s_ws;
    const int tid = threadIdx.x;
    const float* W = (blockIdx.x == 0) ? W1 : W2;
    int8_t* Wq     = (blockIdx.x == 0) ? g_W1q : g_W2q;
    const int n    = (blockIdx.x == 0) ? 128 * 256 : 128 * 128;

    if (tid < 512) g_norm[blockIdx.x * 512 + tid] = 0.0;

    double acc = 0.0;
    for (int i = tid; i < n; i += 1024) acc += (double)fabsf(W[i]);
    red[tid] = acc;
    __syncthreads();
    for (int s = 512; s > 0; s >>= 1) {
        if (tid < s) red[tid] += red[tid + s];
        __syncthreads();
    }
    if (tid == 0) {
        float m  = fmaxf((float)(red[0] / (double)n), EPSF);
        s_ws = 1.0f / m;                 // ref: ws = 1/clip(mean)
        g_wsc[blockIdx.x] = m;           // ref's t/ws (t = +-1) -> t*m
    }
    __syncthreads();
    const float ws = s_ws;
    for (int i = tid; i < n; i += 1024) {
        float t = rintf(W[i] * ws);      // round half-to-even like jnp.round
        t = fminf(1.0f, fmaxf(-1.0f, t));
        Wq[i] = (int8_t)t;
    }
}

// ---------------------------------------------------------------------------
// no-op kernels: keep bitnet_F at the ncu capture slot (stream position 3).
// ---------------------------------------------------------------------------
__global__ void dummy_kernel() {}

// ---------------------------------------------------------------------------
// Kernel 2: fused persistent pass, contiguous tile chunk per CTA.
// Warps fully decoupled; per-warp smem column sums, flushed on batch change.
// ---------------------------------------------------------------------------
__global__ __launch_bounds__(256, 2)
void bitnet_F(const float* __restrict__ evid, const float* __restrict__ prior,
              const float* __restrict__ b1, const float* __restrict__ b2,
              float* __restrict__ out) {
    extern __shared__ unsigned char sm[];
    const uint32_t sb = smem_u32(sm);
    const int tid   = threadIdx.x;
    const int lane  = tid & 31;
    const int w     = tid >> 5;
    const int g     = lane >> 2;   // mma group id (row)
    const int tg    = lane & 3;    // thread-in-group (col/k)
    const int mb    = w * 16;
    const unsigned qmask = 0xFu << (lane & 28);   // this lane's quad

    // ldmatrix per-lane address components
    const int lrow  = lane & 15;
    const int lkoff = (lane >> 4) * 16;
    const int brow  = ((lane >> 4) & 1) * 8 + (lane & 7);
    const int bkoff = ((lane >> 3) & 1) * 16;

    // epi2 staging per-lane coords: 2 rows/instr, 16B per lane within 256B half-row
    const int srow  = lane >> 4;            // 0 or 1
    const int sc16  = lane & 15;            // 16B chunk index

    float* s1arr = (float*)(sm + OFF_S1);
    float* b1s   = (float*)(sm + OFF_B1);
    float* b2l   = (float*)(sm + OFF_B2L);
    float* csw   = (float*)(sm + OFF_CSW) + w * 128;   // warp-private
    const float4* pr4 = (const float4*)prior;
    const float4* ev4 = (const float4*)evid;

    // ---- prologue: weight tiles once ----
#pragma unroll
    for (int i = 0; i < 8; i++) {            // W1: 2048 x 16B
        int c = tid + 256 * i;
        int o = c >> 4, k = c & 15;
        cp16(sb + OFF_W1 + o * W1_STR + k * 16, g_W1q + c * 16);
    }
#pragma unroll
    for (int i = 0; i < 4; i++) {            // W2: 1024 x 16B
        int c = tid + 256 * i;
        int o = c >> 3, k = c & 7;
        cp16(sb + OFF_W2 + o * W2_STR + k * 16, g_W2q + c * 16);
    }
    if (tid < 128) {
        b1s[tid] = __ldg(&b1[tid]);
        b2l[tid] = -__ldg(&b2[tid]) * L2E;   // folded sigmoid bias
    }
#pragma unroll
    for (int c = 0; c < 4; c++) csw[lane + c * 32] = 0.0f;   // zero own csum
    asm volatile("cp.async.commit_group;");
    asm volatile("cp.async.wait_group 0;" ::: "memory");
    __syncthreads();                          // weights/biases visible to all

    const float wsc1 = g_wsc[0];
    const float wsc2 = g_wsc[1];

    // tile-invariant LDSM bases
    const uint32_t aAbase  = sb + OFF_XQ + (mb + lrow) * XQ_STR + lkoff;
    const uint32_t aHbase  = sb + OFF_HQ + (mb + lrow) * HQ_STR + lkoff;
    const uint32_t bW1base = sb + OFF_W1 + brow * W1_STR + bkoff;
    const uint32_t bW2base = sb + OFF_W2 + brow * W2_STR + bkoff;

    // contiguous chunk: batch boundary crossed at most once per CTA
    const int bid    = blockIdx.x;
    const int tstart = bid * BASEQ + (bid < 272 ? bid : 272);
    const int tend   = tstart + BASEQ + (bid < 272 ? 1 : 0);
    int cur_batch = tstart >> 8;               // 256 tiles per batch

    for (int tile = tstart; tile < tend; tile++) {
        const int token0 = tile * 128;
        const int batch  = token0 >> 15;

        if (batch != cur_batch) {              // flush warp csum (rare: <=1x)
            __syncwarp();
#pragma unroll
            for (int c = 0; c < 4; c++) {
                int col = lane + c * 32;
                float v = csw[col];
                if (v != 0.0f) atomicAdd(&g_norm[cur_batch * 128 + col], (double)v);
                csw[col] = 0.0f;
            }
            __syncwarp();
            cur_batch = batch;
        }

        // ---- Phase A: quantize own 16-row band (batch 4 rows, redux max) ----
        {
            const size_t rbase = (size_t)(token0 + mb) * 32;   // float4 units
#pragma unroll
            for (int r0r = 0; r0r < 16; r0r += 4) {
                float4 pa[4], ea[4];
#pragma unroll
                for (int r = 0; r < 4; r++) {
                    pa[r] = __ldg(&pr4[rbase + (size_t)(r0r + r) * 32 + lane]);
                    ea[r] = __ldg(&ev4[rbase + (size_t)(r0r + r) * 32 + lane]);
                }
#pragma unroll
                for (int r = 0; r < 4; r++) {
                    float4 a = pa[r], b = ea[r];
                    float m = fmaxf(fmaxf(fabsf(a.x), fabsf(a.y)),
                                    fmaxf(fabsf(a.z), fabsf(a.w)));
                    m = fmaxf(m, fmaxf(fmaxf(fabsf(b.x), fabsf(b.y)),
                                       fmaxf(fabsf(b.z), fabsf(b.w))));
                    m = __uint_as_float(redux_max(__float_as_uint(m), 0xffffffffu));
                    float s = QBF / fmaxf(m, EPSF);
                    const int row = mb + r0r + r;
                    *(unsigned*)(sm + OFF_XQ + row * XQ_STR + lane * 4) =
                        pack_magic4(a, s);
                    *(unsigned*)(sm + OFF_XQ + row * XQ_STR + 128 + lane * 4) =
                        pack_magic4(b, s);
                    if (lane == 0) s1arr[row] = s;
                }
            }
        }
        __syncwarp();   // band + scales are warp-private

        // ---- GEMM1: [16 x 256] x [256 x 128] per warp, int8 exact ----
        int acc[16][4];
#pragma unroll
        for (int n = 0; n < 16; n++) { acc[n][0] = acc[n][1] = acc[n][2] = acc[n][3] = 0; }
#pragma unroll
        for (int k8 = 0; k8 < 8; k8++) {
            const int kb = k8 * 32;
            unsigned a0, a1, a2, a3;
            ldsm4(a0, a1, a2, a3, aAbase + kb);
#pragma unroll
            for (int n2 = 0; n2 < 8; n2++) {
                unsigned b0, b1r, b2r, b3;
                ldsm4(b0, b1r, b2r, b3, bW1base + (n2 * 16) * W1_STR + kb);
                mma_s8(acc[n2 * 2],     a0, a1, a2, a3, b0,  b1r);
                mma_s8(acc[n2 * 2 + 1], a0, a1, a2, a3, b2r, b3);
            }
        }

        // ---- Epilogue 1: dequant + bias + ReLU, quad redux max, requant ----
        const float dq0 = wsc1 / s1arr[mb + g];
        const float dq1 = wsc1 / s1arr[mb + g + 8];
        float hm0 = 0.0f, hm1 = 0.0f;
#pragma unroll
        for (int n = 0; n < 16; n++) {
            const int col = n * 8 + tg * 2;
            float c0 = fmaxf(0.0f, i2f_magic(acc[n][0]) * dq0 + b1s[col]);
            float c1 = fmaxf(0.0f, i2f_magic(acc[n][1]) * dq0 + b1s[col + 1]);
            float c2 = fmaxf(0.0f, i2f_magic(acc[n][2]) * dq1 + b1s[col]);
            float c3 = fmaxf(0.0f, i2f_magic(acc[n][3]) * dq1 + b1s[col + 1]);
            hm0 = fmaxf(hm0, fmaxf(c0, c1));
            hm1 = fmaxf(hm1, fmaxf(c2, c3));
            acc[n][0] = __float_as_int(c0);
            acc[n][1] = __float_as_int(c1);
            acc[n][2] = __float_as_int(c2);
            acc[n][3] = __float_as_int(c3);
        }
        hm0 = __uint_as_float(redux_max(__float_as_uint(hm0), qmask));
        hm1 = __uint_as_float(redux_max(__float_as_uint(hm1), qmask));
        const float s2_0 = QBF / fmaxf(hm0, EPSF);
        const float s2_1 = QBF / fmaxf(hm1, EPSF);

#pragma unroll
        for (int n = 0; n < 16; n++) {
            unsigned q0 = __float_as_uint(__fadd_rn(__fmul_rn(__int_as_float(acc[n][0]), s2_0), MAGF));
            unsigned q1 = __float_as_uint(__fadd_rn(__fmul_rn(__int_as_float(acc[n][1]), s2_0), MAGF));
            unsigned q2 = __float_as_uint(__fadd_rn(__fmul_rn(__int_as_float(acc[n][2]), s2_1), MAGF));
            unsigned q3 = __float_as_uint(__fadd_rn(__fmul_rn(__int_as_float(acc[n][3]), s2_1), MAGF));
            unsigned short p0 = (unsigned short)__byte_perm(q0, q1, 0x0040);
            unsigned short p1 = (unsigned short)__byte_perm(q2, q3, 0x0040);
            *(unsigned short*)(sm + OFF_HQ + (mb + g)     * HQ_STR + n * 8 + tg * 2) = p0;
            *(unsigned short*)(sm + OFF_HQ + (mb + g + 8) * HQ_STR + n * 8 + tg * 2) = p1;
        }
        __syncwarp();   // each warp reads only its own 16 HQ rows

        // ---- GEMM2: [16 x 128] x [128 x 128] per warp ----
#pragma unroll
        for (int n = 0; n < 16; n++) { acc[n][0] = acc[n][1] = acc[n][2] = acc[n][3] = 0; }
#pragma unroll
        for (int k4 = 0; k4 < 4; k4++) {
            const int kb = k4 * 32;
            unsigned a0, a1, a2, a3;
            ldsm4(a0, a1, a2, a3, aHbase + kb);
#pragma unroll
            for (int n2 = 0; n2 < 8; n2++) {
                unsigned b0, b1r, b2r, b3;
                ldsm4(b0, b1r, b2r, b3, bW2base + (n2 * 16) * W2_STR + kb);
                mma_s8(acc[n2 * 2],     a0, a1, a2, a3, b0,  b1r);
                mma_s8(acc[n2 * 2 + 1], a0, a1, a2, a3, b2r, b3);
            }
        }

        // ---- Epilogue 2: staged through the dead XQ band, per 64-col half ----
        // coalesced LDG prior -> STS; frag-layout LDS/compute/STS in place;
        // coalesced STG out. All warp-private; XQ band = 16 rows x 272B.
        const float dq20 = wsc2 / s2_0;
        const float dq21 = wsc2 / s2_1;
        const float dql0 = -dq20 * L2E;     // exp(-z) = 2^(acc*dql + b2l)
        const float dql1 = -dq21 * L2E;
        const float* prg = prior + (size_t)(token0 + mb) * 128;
        float*       og  = out   + (size_t)(token0 + mb) * 128;

#pragma unroll
        for (int h = 0; h < 2; h++) {
            const int c0 = h * 64;
            // stage prior half-rows (16 rows x 256B), 2 rows per instruction
#pragma unroll
            for (int i = 0; i < 8; i++) {
                int r2 = i * 2 + srow;
                float4 v = __ldg((const float4*)(prg + (size_t)r2 * 128 + c0 + sc16 * 4));
                *(float4*)(sm + OFF_XQ + (mb + r2) * XQ_STR + sc16 * 16) = v;
            }
            __syncwarp();
            // compute u in fragment layout, read prior / write u in place
#pragma unroll
            for (int nn = 0; nn < 8; nn++) {
                const int n   = h * 8 + nn;
                const int col = n * 8 + tg * 2;        // full column index
                const int ch  = nn * 8 + tg * 2;       // column within half
                float e0 = ex2f(i2f_magic(acc[n][0]) * dql0 + b2l[col]);
                float e1 = ex2f(i2f_magic(acc[n][1]) * dql0 + b2l[col + 1]);
                float e2 = ex2f(i2f_magic(acc[n][2]) * dql1 + b2l[col]);
                float e3 = ex2f(i2f_magic(acc[n][3]) * dql1 + b2l[col + 1]);
                float2 pr0 = *(float2*)(sm + OFF_XQ + (mb + g)     * XQ_STR + ch * 4);
                float2 pr1 = *(float2*)(sm + OFF_XQ + (mb + 8 + g) * XQ_STR + ch * 4);
                float u0 = __fdividef(pr0.x, 1.0f + e0);
                float u1 = __fdividef(pr0.y, 1.0f + e1);
                float u2 = __fdividef(pr1.x, 1.0f + e2);
                float u3 = __fdividef(pr1.y, 1.0f + e3);
                *(float2*)(sm + OFF_XQ + (mb + g)     * XQ_STR + ch * 4) = make_float2(u0, u1);
                *(float2*)(sm + OFF_XQ + (mb + 8 + g) * XQ_STR + ch * 4) = make_float2(u2, u3);
                float cs0 = u0 + u2, cs1 = u1 + u3;
                cs0 += __shfl_xor_sync(0xffffffffu, cs0, 4);
                cs0 += __shfl_xor_sync(0xffffffffu, cs0, 8);
                cs0 += __shfl_xor_sync(0xffffffffu, cs0, 16);
                cs1 += __shfl_xor_sync(0xffffffffu, cs1, 4);
                cs1 += __shfl_xor_sync(0xffffffffu, cs1, 8);
                cs1 += __shfl_xor_sync(0xffffffffu, cs1, 16);
                if (g == 0) {
                    csw[col]     += cs0;
                    csw[col + 1] += cs1;
                }
            }
            __syncwarp();
            // coalesced store of u half-rows
#pragma unroll
            for (int i = 0; i < 8; i++) {
                int r2 = i * 2 + srow;
                float4 v = *(float4*)(sm + OFF_XQ + (mb + r2) * XQ_STR + sc16 * 16);
                *(float4*)(og + (size_t)r2 * 128 + c0 + sc16 * 4) = v;
            }
            __syncwarp();   // buffer reusable for next half / next tile
        }
        // no block barrier: all loop-carried smem state is warp-private
    }

    // ---- final flush of warp csum ----
    __syncwarp();
#pragma unroll
    for (int c = 0; c < 4; c++) {
        int col = lane + c * 32;
        float v = csw[col];
        if (v != 0.0f) atomicAdd(&g_norm[cur_batch * 128 + col], (double)v);
    }
}

// ---------------------------------------------------------------------------
__global__ void finalize_norm() {
    int i = threadIdx.x;  // 1024 threads
    g_rnorm[i] = 1.0f / fmaxf((float)g_norm[i], 1e-10f);
}

// ---------------------------------------------------------------------------
__global__ void normalize_kernel(float4* __restrict__ out4) {
    int i = blockIdx.x * 256 + threadIdx.x;    // 8,388,608 float4s
    int b  = i >> 20;                          // 2^20 float4 per batch
    int f4 = i & 31;                           // 32 float4 per feature row
    float4 r = *(const float4*)&g_rnorm[b * 128 + f4 * 4];
    float4 v = out4[i];
    v.x *= r.x; v.y *= r.y; v.z *= r.z; v.w *= r.w;
    out4[i] = v;
}

// ---------------------------------------------------------------------------
extern "C" void kernel_launch(void* const* d_in, const int* in_sizes, int n_in,
                              void* d_out, int out_size) {
    const float* evid  = (const float*)d_in[0];
    const float* prior = (const float*)d_in[1];
    const float* W1    = (const float*)d_in[2];
    const float* b1    = (const float*)d_in[3];
    const float* W2    = (const float*)d_in[4];
    const float* b2    = (const float*)d_in[5];
    float* out = (float*)d_out;

    cudaFuncSetAttribute(bitnet_F, cudaFuncAttributeMaxDynamicSharedMemorySize,
                         SMEM_BYTES);

    prep_kernel<<<2, 1024>>>(W1, W2);
    dummy_kernel<<<1, 32>>>();                 // capture-window alignment
    dummy_kernel<<<1, 32>>>();                 // (bitnet_F -> stream pos 3)
    bitnet_F<<<GRIDP, 256, SMEM_BYTES>>>(evid, prior, b1, b2, out);
    finalize_norm<<<1, 1024>>>();
    normalize_kernel<<<out_size / 1024, 256>>>((float4*)out);
}